// round 11
// baseline (speedup 1.0000x reference)
#include <cuda_runtime.h>
#include <cuda_fp16.h>
#include <cuda_bf16.h>

// B=4096 scenes, L=200 padded, V=50000, H=128.
// out[i,h] = b[h] + sum_{j<len_i} W[h, tokens[i,j]]
// R10: flat equal-size work units. Unit = (scene, 32-token chunk), one warp
// each (grid 4096*7). Partials to scratch, then per-scene reduce kernel.
// Removes ragged per-scene block imbalance / block-reduce / tail effects
// that R5-R9 showed were the residual (no pipe >35% busy, time invariant
// to instr count and MLP). Deterministic: no atomics.

#define B_N 4096
#define L_N 200
#define V_N 50000
#define H_N 128
#define CHUNKS 7                 // ceil(200/32)
#define UNITS (B_N * CHUNKS)     // 28672

__device__ __half g_Wt[(size_t)V_N * H_N];          // 12.8 MB transposed weights
__device__ float  g_partial[(size_t)UNITS * H_N];   // 14.7 MB partial sums

// ---------------------------------------------------------------------------
// Tiled transpose+convert: W[H,V] fp32 -> g_Wt[V,H] fp16. half2 stores.
// ---------------------------------------------------------------------------
__global__ void __launch_bounds__(256) transpose_W_kernel(const float* __restrict__ W) {
    __shared__ float tile[32][33];
    int v0 = blockIdx.x * 32;
    int h0 = blockIdx.y * 32;
    int x = threadIdx.x;          // 0..31
    int y = threadIdx.y;          // 0..7

    #pragma unroll
    for (int i = 0; i < 32; i += 8) {
        int v = v0 + x;
        int h = h0 + y + i;
        if (v < V_N) tile[y + i][x] = W[(size_t)h * V_N + v];
    }
    __syncthreads();

    int tid = threadIdx.y * 32 + threadIdx.x;   // 0..255
    int hp  = tid & 15;                         // h-pair index 0..15
    #pragma unroll
    for (int iter = 0; iter < 2; iter++) {
        int vloc = iter * 16 + (tid >> 4);      // 0..31
        int v = v0 + vloc;
        if (v < V_N) {
            __half2 val = __floats2half2_rn(tile[2 * hp][vloc], tile[2 * hp + 1][vloc]);
            *reinterpret_cast<__half2*>(&g_Wt[(size_t)v * H_N + h0 + 2 * hp]) = val;
        }
    }
}

// ---------------------------------------------------------------------------
// Partial gather: one warp per unit = (scene, chunk of 32 tokens).
// Lane owns h = 4*lane..4*lane+3 (uint2 = 4 halves). One token per
// warp-LDG.64; batches of 8 (MLP 8); chain-4 HADD2 groups flushed to fp32.
// Inactive units (chunk beyond len) exit immediately.
// ---------------------------------------------------------------------------
__global__ void __launch_bounds__(128, 10) bow_partial_kernel(
    const int* __restrict__ tokens,
    const int* __restrict__ lengths)
{
    int unit = blockIdx.x * 4 + (threadIdx.x >> 5);   // grid is exact: UNITS/4 blocks
    int lane = threadIdx.x & 31;

    int scene = unit / CHUNKS;
    int chunk = unit - scene * CHUNKS;
    int len = lengths[scene];
    int base = chunk * 32;
    if (base >= len) return;                          // inactive unit

    int m = len - base;
    if (m > 32) m = 32;

    const int* tok = tokens + (size_t)scene * L_N;
    const char* WtB = reinterpret_cast<const char*>(g_Wt);
    unsigned laneOff = (unsigned)lane * 8u;           // lane's 4 halves in 256B row

    int jj = base + lane;
    int myTok = tok[jj < L_N ? jj : (L_N - 1)];       // coalesced chunk of tokens

    float4 acc = make_float4(0.f, 0.f, 0.f, 0.f);

    if (m == 32) {
        #pragma unroll
        for (int kk = 0; kk < 32; kk += 8) {
            uint2 w[8];
            #pragma unroll
            for (int k = 0; k < 8; k++) {
                int t = __shfl_sync(0xffffffffu, myTok, kk + k);
                w[k] = *reinterpret_cast<const uint2*>(WtB + (unsigned)t * 256u + laneOff);
            }
            #pragma unroll
            for (int g = 0; g < 2; g++) {
                uint2* wg = &w[4 * g];
                __half2 a0 = *reinterpret_cast<__half2*>(&wg[0].x);
                __half2 a1 = *reinterpret_cast<__half2*>(&wg[0].y);
                #pragma unroll
                for (int k = 1; k < 4; k++) {
                    a0 = __hadd2(a0, *reinterpret_cast<__half2*>(&wg[k].x));
                    a1 = __hadd2(a1, *reinterpret_cast<__half2*>(&wg[k].y));
                }
                float2 f01 = __half22float2(a0);
                float2 f23 = __half22float2(a1);
                acc.x += f01.x; acc.y += f01.y;
                acc.z += f23.x; acc.w += f23.y;
            }
        }
    } else {
        for (int k = 0; k < m; k++) {
            int t = __shfl_sync(0xffffffffu, myTok, k);
            uint2 w = *reinterpret_cast<const uint2*>(WtB + (unsigned)t * 256u + laneOff);
            float2 f01 = __half22float2(*reinterpret_cast<__half2*>(&w.x));
            float2 f23 = __half22float2(*reinterpret_cast<__half2*>(&w.y));
            acc.x += f01.x; acc.y += f01.y;
            acc.z += f23.x; acc.w += f23.y;
        }
    }

    reinterpret_cast<float4*>(g_partial + (size_t)unit * H_N)[lane] = acc;
}

// ---------------------------------------------------------------------------
// Reduce: one warp per scene sums its active chunk partials + bias -> out.
// ---------------------------------------------------------------------------
__global__ void __launch_bounds__(128) bow_reduce_kernel(
    const int* __restrict__ lengths,
    const float* __restrict__ bias,
    float* __restrict__ out)
{
    int scene = blockIdx.x * 4 + (threadIdx.x >> 5);  // grid exact: B_N/4
    int lane  = threadIdx.x & 31;

    int len = lengths[scene];
    int nact = (len + 31) >> 5;                       // active chunks, 0..7

    float4 acc = reinterpret_cast<const float4*>(bias)[lane];
    const float4* p4 = reinterpret_cast<const float4*>(g_partial + (size_t)scene * CHUNKS * H_N);
    for (int c = 0; c < nact; c++) {
        float4 p = p4[c * 32 + lane];
        acc.x += p.x; acc.y += p.y; acc.z += p.z; acc.w += p.w;
    }
    reinterpret_cast<float4*>(out + (size_t)scene * H_N)[lane] = acc;
}

// ---------------------------------------------------------------------------
extern "C" void kernel_launch(void* const* d_in, const int* in_sizes, int n_in,
                              void* d_out, int out_size) {
    const int*   tokens  = (const int*)d_in[0];
    const int*   lengths = (const int*)d_in[1];
    const float* W       = (const float*)d_in[2];
    const float* bias    = (const float*)d_in[3];
    float*       out     = (float*)d_out;

    (void)in_sizes; (void)n_in; (void)out_size;

    dim3 tgrid((V_N + 31) / 32, H_N / 32);
    dim3 tblock(32, 8);
    transpose_W_kernel<<<tgrid, tblock>>>(W);

    bow_partial_kernel<<<UNITS / 4, 128>>>(tokens, lengths);
    bow_reduce_kernel<<<B_N / 4, 128>>>(lengths, bias, out);
}

// round 13
// speedup vs baseline: 1.0552x; 1.0552x over previous
#include <cuda_runtime.h>
#include <cuda_fp16.h>
#include <cuda_bf16.h>

// B=4096 scenes, L=200 padded, V=50000, H=128.
// out[i,h] = b[h] + sum_{j<len_i} W[h, tokens[i,j]]
// R12 = R11 with the transpose smem stride fixed: 129 -> 132 floats so row
// starts are 16B-aligned (LDS.128 trapped 'misaligned address' at stride 129).
// Gather: software-pipelined double-buffered 8-deep LDG.64 batches.

#define B_N 4096
#define L_N 200
#define V_N 50000
#define H_N 128

__device__ __half g_Wt[(size_t)V_N * H_N];   // 12.8 MB scratch, [V,H] row-major

// ---------------------------------------------------------------------------
// Transpose+convert: W[H,V] fp32 -> g_Wt[V,H] fp16.
// One block per 32-v slab covers ALL 128 h: writes full 256B rows.
// smem tile [v][h] stride 132 floats (528B: 16B-aligned rows for LDS.128).
// ---------------------------------------------------------------------------
__global__ void __launch_bounds__(256) transpose_W_kernel(const float* __restrict__ W) {
    __shared__ float s[32][132];
    int v0   = blockIdx.x * 32;
    int w    = threadIdx.x >> 5;    // warp 0..7
    int lane = threadIdx.x & 31;

    // Read: h-row h = 8i + w, lane reads W[h][v0+lane] (coalesced 128B).
    int v = v0 + lane;
    bool vok = (v < V_N);
    #pragma unroll
    for (int i = 0; i < 16; i++) {
        int h = i * 8 + w;
        s[lane][h] = vok ? W[(size_t)h * V_N + v] : 0.f;
    }
    __syncthreads();

    // Write: warp w handles v-rows w, w+8, w+16, w+24.
    // Lane converts s[vr][4*lane..+3] (LDS.128, conflict-free) -> uint2;
    // 32 lanes = full 256B coalesced store row.
    #pragma unroll
    for (int i = 0; i < 4; i++) {
        int vr = i * 8 + w;
        int vg = v0 + vr;
        if (vg < V_N) {
            float4 f = *reinterpret_cast<const float4*>(&s[vr][4 * lane]);
            __half2 lo = __floats2half2_rn(f.x, f.y);
            __half2 hi = __floats2half2_rn(f.z, f.w);
            uint2 val;
            val.x = *reinterpret_cast<unsigned*>(&lo);
            val.y = *reinterpret_cast<unsigned*>(&hi);
            *reinterpret_cast<uint2*>(&g_Wt[(size_t)vg * H_N + 4 * lane]) = val;
        }
    }
}

// ---------------------------------------------------------------------------
// Gather-sum: one block (4 warps) per scene; warp w owns 32-token chunks at
// 32w, striding 128. Lane owns h = 4*lane..4*lane+3 (uint2 = 4 halves).
// Full chunks: double-buffered batches of 8 LDG.64 -- issue batch b+1 before
// accumulating batch b (chain-4 HADD2 x2 groups, flushed to fp32).
// ---------------------------------------------------------------------------
__global__ void __launch_bounds__(128, 9) bow_gather_kernel(
    const int* __restrict__ tokens,
    const int* __restrict__ lengths,
    const float* __restrict__ bias,
    float* __restrict__ out)
{
    __shared__ float4 sh[3][32];

    int scene = blockIdx.x;
    int wid   = threadIdx.x >> 5;
    int lane  = threadIdx.x & 31;

    int len = lengths[scene];
    const int* tok = tokens + (size_t)scene * L_N;
    const char* WtB = reinterpret_cast<const char*>(g_Wt);
    unsigned laneOff = (unsigned)lane * 8u;   // byte offset of lane's 4 halves

    float4 acc = make_float4(0.f, 0.f, 0.f, 0.f);

    for (int base = wid * 32; base < len; base += 128) {
        int m = len - base;
        if (m > 32) m = 32;
        int jj = base + lane;
        int myTok = tok[jj < L_N ? jj : (L_N - 1)];   // coalesced chunk

        if (m == 32) {
            uint2 wbuf[2][8];
            // Prologue: batch 0 in flight.
            #pragma unroll
            for (int k = 0; k < 8; k++) {
                int t = __shfl_sync(0xffffffffu, myTok, k);
                wbuf[0][k] = *reinterpret_cast<const uint2*>(WtB + (unsigned)t * 256u + laneOff);
            }
            #pragma unroll
            for (int b = 0; b < 4; b++) {
                int cur = b & 1, nxt = cur ^ 1;
                if (b < 3) {
                    // Issue next batch BEFORE accumulating current.
                    #pragma unroll
                    for (int k = 0; k < 8; k++) {
                        int t = __shfl_sync(0xffffffffu, myTok, 8 * (b + 1) + k);
                        wbuf[nxt][k] = *reinterpret_cast<const uint2*>(WtB + (unsigned)t * 256u + laneOff);
                    }
                }
                // Accumulate current: two chain-4 fp16 groups -> fp32.
                #pragma unroll
                for (int g = 0; g < 2; g++) {
                    uint2* wg = &wbuf[cur][4 * g];
                    __half2 a0 = *reinterpret_cast<__half2*>(&wg[0].x);
                    __half2 a1 = *reinterpret_cast<__half2*>(&wg[0].y);
                    #pragma unroll
                    for (int k = 1; k < 4; k++) {
                        a0 = __hadd2(a0, *reinterpret_cast<__half2*>(&wg[k].x));
                        a1 = __hadd2(a1, *reinterpret_cast<__half2*>(&wg[k].y));
                    }
                    float2 f01 = __half22float2(a0);
                    float2 f23 = __half22float2(a1);
                    acc.x += f01.x; acc.y += f01.y;
                    acc.z += f23.x; acc.w += f23.y;
                }
            }
        } else {
            for (int k = 0; k < m; k++) {
                int t = __shfl_sync(0xffffffffu, myTok, k);
                uint2 w = *reinterpret_cast<const uint2*>(WtB + (unsigned)t * 256u + laneOff);
                float2 f01 = __half22float2(*reinterpret_cast<__half2*>(&w.x));
                float2 f23 = __half22float2(*reinterpret_cast<__half2*>(&w.y));
                acc.x += f01.x; acc.y += f01.y;
                acc.z += f23.x; acc.w += f23.y;
            }
        }
    }

    // Block reduce: warps 1-3 -> smem, warp 0 combines + bias + store.
    if (wid != 0) sh[wid - 1][lane] = acc;
    __syncthreads();
    if (wid == 0) {
        float4 b4 = reinterpret_cast<const float4*>(bias)[lane];
        #pragma unroll
        for (int w = 0; w < 3; w++) {
            float4 p = sh[w][lane];
            acc.x += p.x; acc.y += p.y; acc.z += p.z; acc.w += p.w;
        }
        acc.x += b4.x; acc.y += b4.y; acc.z += b4.z; acc.w += b4.w;
        reinterpret_cast<float4*>(out + (size_t)scene * H_N)[lane] = acc;
    }
}

// ---------------------------------------------------------------------------
extern "C" void kernel_launch(void* const* d_in, const int* in_sizes, int n_in,
                              void* d_out, int out_size) {
    const int*   tokens  = (const int*)d_in[0];
    const int*   lengths = (const int*)d_in[1];
    const float* W       = (const float*)d_in[2];
    const float* bias    = (const float*)d_in[3];
    float*       out     = (float*)d_out;

    (void)in_sizes; (void)n_in; (void)out_size;

    transpose_W_kernel<<<(V_N + 31) / 32, 256>>>(W);
    bow_gather_kernel<<<B_N, 128>>>(tokens, lengths, bias, out);
}